// round 13
// baseline (speedup 1.0000x reference)
#include <cuda_runtime.h>
#include <cuda_bf16.h>
#include <cuda_fp16.h>
#include <cstdint>
#include <math.h>

#define NN 50000
#define DD 128
#define EE 625000
#define SCAN_BLOCKS 49                     // ceil(50000/1024)
#define DEG_BLOCKS ((EE + 255) / 256)      // 2442
#define TAN_BLOCKS ((4 * NN) / 8)          // 25000
#define G1_BLOCKS ((NN + 127) / 128)       // 391

// ---------------- scratch (static device allocations) ----------------------
__device__ __nv_bfloat16 g_A1hi[NN * DD];
__device__ __nv_bfloat16 g_A1lo[NN * DD];
__device__ __nv_bfloat16 g_A2hi[NN * 3 * DD];    // [n][k*128+i]
__device__ __nv_bfloat16 g_A2lo[NN * 3 * DD];
__device__ __nv_bfloat16 g_W1hi[DD * DD];
__device__ __nv_bfloat16 g_W1lo[DD * DD];
__device__ __nv_bfloat16 g_W2hi[DD * 3 * DD];    // [o][k*128+i]
__device__ __nv_bfloat16 g_W2lo[DD * 3 * DD];
__device__ __half g_transformed[NN * DD];        // fp16: gather-only consumer
__device__ float g_conv[NN * DD];
__device__ int   g_deg[NN];        // zero at load; scan3 restores zeros per run
__device__ int   g_rowstart[NN + 1];
__device__ int   g_cursor[NN];
__device__ int   g_csr[EE];
__device__ int   g_bsum[SCAN_BLOCKS];
__device__ int   g_boff[SCAN_BLOCKS];
__device__ int   g_ticket;         // zero at load; scan12 last block restores

#define SMEM_SWIZZLE_128B(b) ((b) ^ (((b) >> 3) & 0x70))

__device__ __forceinline__ uint32_t smem_to_u32(const void* p) {
    uint32_t a;
    asm("{ .reg .u64 t; cvta.to.shared.u64 t, %1; cvt.u32.u64 %0, t; }"
        : "=r"(a) : "l"(p));
    return a;
}
__device__ __forceinline__ void cp_async16(uint32_t saddr, const void* gptr) {
    asm volatile("cp.async.cg.shared.global [%0], [%1], 16;"
                 :: "r"(saddr), "l"(gptr) : "memory");
}
__device__ __forceinline__ void cp_commit() {
    asm volatile("cp.async.commit_group;" ::: "memory");
}
template <int N>
__device__ __forceinline__ void cp_wait() {
    asm volatile("cp.async.wait_group %0;" :: "n"(N) : "memory");
}
__device__ __forceinline__ void ldsm_x4(uint32_t* r, uint32_t addr) {
    asm volatile("ldmatrix.sync.aligned.m8n8.x4.shared.b16 {%0,%1,%2,%3}, [%4];"
                 : "=r"(r[0]), "=r"(r[1]), "=r"(r[2]), "=r"(r[3])
                 : "r"(addr));
}
__device__ __forceinline__ void mma_bf16(float* d, const uint32_t* a,
                                         const uint32_t* b) {
    asm volatile(
        "mma.sync.aligned.m16n8k16.row.col.f32.bf16.bf16.f32 "
        "{%0,%1,%2,%3}, {%4,%5,%6,%7}, {%8,%9}, {%0,%1,%2,%3};"
        : "+f"(d[0]), "+f"(d[1]), "+f"(d[2]), "+f"(d[3])
        : "r"(a[0]), "r"(a[1]), "r"(a[2]), "r"(a[3]), "r"(b[0]), "r"(b[1]));
}
__device__ __forceinline__ void split_bf16(float v, __nv_bfloat16& hi, __nv_bfloat16& lo) {
    hi = __float2bfloat16(v);
    lo = __float2bfloat16(v - __bfloat162float(hi));
}

// ---------------- K-W: weight split only (off critical path, on s2) ---------
__global__ void prep_w_kernel(const float* __restrict__ lin_w,
                              const float* __restrict__ conv_w) {
    int idx = blockIdx.x * blockDim.x + threadIdx.x;   // 0 .. 65535
    if (idx < DD * DD) {
        split_bf16(lin_w[idx], g_W1hi[idx], g_W1lo[idx]);
    } else if (idx < DD * DD + 3 * DD * DD) {
        int t = idx - DD * DD;          // target index in [o][k*128+i]
        int o = t / (3 * DD);
        int r = t - o * (3 * DD);
        int k = r >> 7, i = r & 127;
        split_bf16(conv_w[(o * DD + i) * 3 + k], g_W2hi[t], g_W2lo[t]);
    }
}

// ---------------- K2: fused deg-count + logmap0->bf16 hi/lo -----------------
// (g_deg is all-zero on entry: static init on first run, scan3 restore after)
__global__ void tangent_deg_kernel(const float* __restrict__ node,
                                   const float* __restrict__ h1,
                                   const float* __restrict__ h2,
                                   const float* __restrict__ h3,
                                   const float* __restrict__ curv,
                                   const int* __restrict__ edst) {
    if (blockIdx.x < DEG_BLOCKS) {
        int e = blockIdx.x * 256 + threadIdx.x;
        if (e < EE) atomicAdd(&g_deg[edst[e]], 1);
        return;
    }
    int rid  = ((blockIdx.x - DEG_BLOCKS) << 3) + (threadIdx.x >> 5);
    int lane = threadIdx.x & 31;
    if (rid >= 4 * NN) return;

    const float* srcp;
    int n = 0, k = 0;
    bool is_node = (rid < NN);
    if (is_node) {
        n = rid;
        srcp = node + (size_t)n * DD;
    } else {
        int t = rid - NN;
        k = t / NN;
        n = t - k * NN;
        const float* h = (k == 0) ? h1 : (k == 1) ? h2 : h3;
        srcp = h + (size_t)n * DD;
    }

    float4 x = ((const float4*)srcp)[lane];
    float ss = x.x * x.x + x.y * x.y + x.z * x.z + x.w * x.w;
#pragma unroll
    for (int off = 16; off; off >>= 1) ss += __shfl_xor_sync(0xffffffffu, ss, off);

    float c  = fabsf(curv[0]);
    float sc = sqrtf(c);
    float xn  = fmaxf(sqrtf(ss), 1e-15f);
    float arg = fminf(sc * xn, 1.0f - 1e-5f);
    float alpha = atanhf(arg) / (sc * xn);

    float v[4] = {x.x * alpha, x.y * alpha, x.z * alpha, x.w * alpha};
    union { __nv_bfloat16 b[4]; uint2 u; } ph, pl;
#pragma unroll
    for (int t = 0; t < 4; t++) split_bf16(v[t], ph.b[t], pl.b[t]);

    if (is_node) {
        ((uint2*)(g_A1hi + (size_t)n * DD))[lane] = ph.u;
        ((uint2*)(g_A1lo + (size_t)n * DD))[lane] = pl.u;
    } else {
        size_t off = (size_t)n * (3 * DD) + k * DD + lane * 4;
        *(uint2*)(g_A2hi + off) = ph.u;
        *(uint2*)(g_A2lo + off) = pl.u;
    }
}

// ---------------- K3: scan phase 1 + (last block, 1 warp) phase 2 -----------
__global__ __launch_bounds__(1024) void scan12_kernel() {
    __shared__ int wsum[32];
    __shared__ int s_last;
    int tid = threadIdx.x, lane = tid & 31, w = tid >> 5;
    int idx = blockIdx.x * 1024 + tid;
    int v = (idx < NN) ? g_deg[idx] : 0;
    int x = v;
#pragma unroll
    for (int off = 16; off; off >>= 1) x += __shfl_xor_sync(0xffffffffu, x, off);
    if (lane == 0) wsum[w] = x;
    __syncthreads();
    if (w == 0) {
        int z = wsum[lane];
#pragma unroll
        for (int off = 16; off; off >>= 1) z += __shfl_xor_sync(0xffffffffu, z, off);
        if (lane == 0) g_bsum[blockIdx.x] = z;
    }
    __threadfence();
    if (tid == 0) {
        int t = atomicAdd(&g_ticket, 1);
        s_last = (t == (int)gridDim.x - 1);
    }
    __syncthreads();
    if (s_last && w == 0) {
        int v0 = (lane < SCAN_BLOCKS) ? g_bsum[lane] : 0;
        int v1 = (lane + 32 < SCAN_BLOCKS) ? g_bsum[lane + 32] : 0;
        int x0 = v0, x1 = v1;
#pragma unroll
        for (int off = 1; off < 32; off <<= 1) {
            int y0 = __shfl_up_sync(0xffffffffu, x0, off);
            int y1 = __shfl_up_sync(0xffffffffu, x1, off);
            if (lane >= off) { x0 += y0; x1 += y1; }
        }
        int tot0 = __shfl_sync(0xffffffffu, x0, 31);
        x1 += tot0;
        g_boff[lane] = x0 - v0;
        if (lane + 32 < SCAN_BLOCKS) g_boff[lane + 32] = x1 - v1;
        if (lane == 0) { g_rowstart[0] = 0; g_ticket = 0; }   // restore for replay
    }
}

// ---------------- K4: block-local scan + offset; restores deg zeros ---------
__global__ __launch_bounds__(1024) void scan3_kernel() {
    __shared__ int wsum[32];
    int tid = threadIdx.x, lane = tid & 31, w = tid >> 5;
    int idx = blockIdx.x * 1024 + tid;
    int v = (idx < NN) ? g_deg[idx] : 0;
    int x = v;
#pragma unroll
    for (int off = 1; off < 32; off <<= 1) {
        int y = __shfl_up_sync(0xffffffffu, x, off);
        if (lane >= off) x += y;
    }
    if (lane == 31) wsum[w] = x;
    __syncthreads();
    if (w == 0) {
        int z = wsum[lane];
#pragma unroll
        for (int off = 1; off < 32; off <<= 1) {
            int y = __shfl_up_sync(0xffffffffu, z, off);
            if (lane >= off) z += y;
        }
        wsum[lane] = z;
    }
    __syncthreads();
    int incl = x + ((w > 0) ? wsum[w - 1] : 0) + g_boff[blockIdx.x];
    if (idx < NN) {
        g_rowstart[idx + 1] = incl;
        g_cursor[idx]       = incl - v;
        g_deg[idx]          = 0;       // restore zeros for next replay
    }
}

// ---------------- K5: place edges into CSR ----------------------------------
__global__ void place_kernel(const int* __restrict__ src,
                             const int* __restrict__ dst) {
    int e = blockIdx.x * blockDim.x + threadIdx.x;
    if (e < EE) {
        int d = dst[e];
        int p = atomicAdd(&g_cursor[d], 1);
        g_csr[p] = src[e];
    }
}

// ---------------- K6: fused HMMA GEMMs (R10 inner loop, fresh-b passes) ------
static constexpr int ST_AHI = 0;
static constexpr int ST_ALO = 16384;
static constexpr int ST_WHI = 32768;
static constexpr int ST_WLO = 49152;
static constexpr int ST_STRIDE = 65536;
static constexpr int SM_BIAS_OFF = 2 * ST_STRIDE;          // 131072
static constexpr int SM_GEMM_TOTAL = SM_BIAS_OFF + 512;    // 131584

template <int K, bool OUT_HALF>
__device__ __forceinline__ void gemm_body(
    int blk, char* smem, uint32_t sb,
    const __nv_bfloat16* Ahi, const __nv_bfloat16* Alo,
    const __nv_bfloat16* Whi, const __nv_bfloat16* Wlo,
    void* out_v, const float* bias) {
    constexpr int CH = K / 64;
    constexpr int KV = K / 8;

    int tid = threadIdx.x;
    int wid = tid >> 5;
    int lane = tid & 31;
    int warp_m = wid & 3;
    int warp_n = wid >> 2;
    int g  = lane >> 3;
    int ri = lane & 7;

    const uint4* A4hi = (const uint4*)Ahi;
    const uint4* A4lo = (const uint4*)Alo;
    const uint4* W4hi = (const uint4*)Whi;
    const uint4* W4lo = (const uint4*)Wlo;

    if (tid < 128) ((float*)(smem + SM_BIAS_OFF))[tid] = bias[tid];

    int base = blk * 128;

    auto prefetch = [&](int c, int buf) {
        uint32_t st = sb + buf * ST_STRIDE;
#pragma unroll
        for (int it = 0; it < 4; ++it) {
            int idx = tid + it * 256;
            int row = idx >> 3;
            int kq  = idx & 7;
            uint32_t off = SMEM_SWIZZLE_128B((uint32_t)(row * 128 + kq * 16));
            int gn = base + row;
            if (gn >= NN) gn = NN - 1;
            size_t gidx = (size_t)gn * KV + c * 8 + kq;
            size_t widx = (size_t)row * KV + c * 8 + kq;
            cp_async16(st + ST_AHI + off, A4hi + gidx);
            cp_async16(st + ST_ALO + off, A4lo + gidx);
            cp_async16(st + ST_WHI + off, W4hi + widx);
            cp_async16(st + ST_WLO + off, W4lo + widx);
        }
        cp_commit();
    };

    float acc[2][8][4];
#pragma unroll
    for (int mi = 0; mi < 2; mi++)
#pragma unroll
        for (int nb = 0; nb < 8; nb++)
#pragma unroll
            for (int q = 0; q < 4; q++) acc[mi][nb][q] = 0.f;

    prefetch(0, 0);

    for (int c = 0; c < CH; ++c) {
        if (c + 1 < CH) {
            prefetch(c + 1, (c + 1) & 1);
            cp_wait<1>();
        } else {
            cp_wait<0>();
        }
        __syncthreads();

        uint32_t st = sb + (c & 1) * ST_STRIDE;

#pragma unroll
        for (int ks = 0; ks < 4; ++ks) {
            uint32_t a_hi[2][4], a_lo[2][4];
#pragma unroll
            for (int mi = 0; mi < 2; ++mi) {
                int row = warp_m * 32 + mi * 16 + ((g & 1) << 3) + ri;
                int kb  = ks * 32 + ((g >> 1) << 4);
                uint32_t off = SMEM_SWIZZLE_128B((uint32_t)(row * 128 + kb));
                ldsm_x4(a_hi[mi], st + ST_AHI + off);
                ldsm_x4(a_lo[mi], st + ST_ALO + off);
            }
#pragma unroll
            for (int pp = 0; pp < 3; ++pp) {
                uint32_t woff = (pp == 1) ? (uint32_t)ST_WLO : (uint32_t)ST_WHI;
                uint32_t (*af)[4] = (pp == 2) ? a_lo : a_hi;
                uint32_t b[8][2];
#pragma unroll
                for (int nb2 = 0; nb2 < 4; ++nb2) {
                    int row = warp_n * 64 + nb2 * 16 + ((g >> 1) << 3) + ri;
                    int kb  = ks * 32 + ((g & 1) << 4);
                    uint32_t off = SMEM_SWIZZLE_128B((uint32_t)(row * 128 + kb));
                    uint32_t r[4];
                    ldsm_x4(r, st + woff + off);
                    b[nb2 * 2 + 0][0] = r[0];
                    b[nb2 * 2 + 0][1] = r[1];
                    b[nb2 * 2 + 1][0] = r[2];
                    b[nb2 * 2 + 1][1] = r[3];
                }
#pragma unroll
                for (int mi = 0; mi < 2; ++mi)
#pragma unroll
                    for (int nb = 0; nb < 8; ++nb)
                        mma_bf16(acc[mi][nb], af[mi], b[nb]);
            }
        }
        __syncthreads();
    }

    const float* bias_s = (const float*)(smem + SM_BIAS_OFF);
    int qrow = lane >> 2;
    int qcol = (lane & 3) * 2;
#pragma unroll
    for (int mi = 0; mi < 2; ++mi) {
#pragma unroll
        for (int nb = 0; nb < 8; ++nb) {
            int col = warp_n * 64 + nb * 8 + qcol;
            float b0 = bias_s[col], b1 = bias_s[col + 1];
            int r0 = base + warp_m * 32 + mi * 16 + qrow;
            int r1 = r0 + 8;
            if (OUT_HALF) {
                __half* out = (__half*)out_v;
                if (r0 < NN)
                    *(__half2*)(out + (size_t)r0 * DD + col) =
                        __floats2half2_rn(acc[mi][nb][0] + b0, acc[mi][nb][1] + b1);
                if (r1 < NN)
                    *(__half2*)(out + (size_t)r1 * DD + col) =
                        __floats2half2_rn(acc[mi][nb][2] + b0, acc[mi][nb][3] + b1);
            } else {
                float* out = (float*)out_v;
                if (r0 < NN)
                    *(float2*)(out + (size_t)r0 * DD + col) =
                        make_float2(acc[mi][nb][0] + b0, acc[mi][nb][1] + b1);
                if (r1 < NN)
                    *(float2*)(out + (size_t)r1 * DD + col) =
                        make_float2(acc[mi][nb][2] + b0, acc[mi][nb][3] + b1);
            }
        }
    }
}

// GEMM2 blocks first (longest-first packing; short G1 CTAs fill the tail wave).
__global__ __launch_bounds__(256)
void gemm_fused_kernel(const float* __restrict__ lin_b,
                       const float* __restrict__ conv_b) {
    extern __shared__ char smem[];
    uint32_t sb = smem_to_u32(smem);
    if (blockIdx.x < G1_BLOCKS) {
        gemm_body<384, false>(blockIdx.x, smem, sb, g_A2hi, g_A2lo,
                              g_W2hi, g_W2lo, g_conv, conv_b);
    } else {
        gemm_body<128, true>(blockIdx.x - G1_BLOCKS, smem, sb,
                             g_A1hi, g_A1lo, g_W1hi, g_W1lo,
                             g_transformed, lin_b);
    }
}

// ---------------- K7: gather(fp16) + mean + conv add + expmap0 ---------------
__global__ void finalize_kernel(const float* __restrict__ curv,
                                float* __restrict__ out) {
    int n = (blockIdx.x * blockDim.x + threadIdx.x) >> 5;
    int lane = threadIdx.x & 31;
    if (n >= NN) return;

    int s = g_rowstart[n];
    int e = g_rowstart[n + 1];
    const uint2* T = (const uint2*)g_transformed;   // 4 halves per lane

    float4 a = make_float4(0.f, 0.f, 0.f, 0.f);
    int p = s;
    for (; p + 4 <= e; p += 4) {
        int i0 = g_csr[p + 0], i1 = g_csr[p + 1];
        int i2 = g_csr[p + 2], i3 = g_csr[p + 3];
        uint2 u0 = T[i0 * 32 + lane];
        uint2 u1 = T[i1 * 32 + lane];
        uint2 u2 = T[i2 * 32 + lane];
        uint2 u3 = T[i3 * 32 + lane];
        __half2 h;
        float2 f;
#define ACC_U(u) \
        h = *(__half2*)&(u).x; f = __half22float2(h); a.x += f.x; a.y += f.y; \
        h = *(__half2*)&(u).y; f = __half22float2(h); a.z += f.x; a.w += f.y;
        ACC_U(u0) ACC_U(u1) ACC_U(u2) ACC_U(u3)
    }
    for (; p < e; ++p) {
        int i0 = g_csr[p];
        uint2 u0 = T[i0 * 32 + lane];
        __half2 h;
        float2 f;
        ACC_U(u0)
#undef ACC_U
    }

    float inv = (e > s) ? 1.0f / (float)(e - s) : 0.0f;
    float4 cv = ((const float4*)g_conv)[n * 32 + lane];
    float4 v = make_float4(cv.x + a.x * inv, cv.y + a.y * inv,
                           cv.z + a.z * inv, cv.w + a.w * inv);

    float ss = v.x * v.x + v.y * v.y + v.z * v.z + v.w * v.w;
#pragma unroll
    for (int off = 16; off; off >>= 1) ss += __shfl_xor_sync(0xffffffffu, ss, off);

    float c  = fabsf(curv[0]);
    float sc = sqrtf(c);
    float un = fmaxf(sqrtf(ss), 1e-15f);
    float arg = sc * un;
    float f2 = tanhf(arg) / arg;

    ((float4*)out)[n * 32 + lane] =
        make_float4(v.x * f2, v.y * f2, v.z * f2, v.w * f2);
}

// ---------------- launch: fork s2 FIRST, then weight-prep + CSR on it --------
extern "C" void kernel_launch(void* const* d_in, const int* in_sizes, int n_in,
                              void* d_out, int out_size) {
    const float* node   = (const float*)d_in[0];
    const float* h1     = (const float*)d_in[1];
    const float* h2     = (const float*)d_in[2];
    const float* h3     = (const float*)d_in[3];
    const float* lin_w  = (const float*)d_in[4];
    const float* lin_b  = (const float*)d_in[5];
    const float* conv_w = (const float*)d_in[6];
    const float* conv_b = (const float*)d_in[7];
    const float* curv   = (const float*)d_in[8];
    const int*   esrc   = (const int*)d_in[9];
    const int*   edst   = (const int*)d_in[10];
    float* out = (float*)d_out;

    static cudaStream_t s2 = nullptr;
    static cudaEvent_t ev0 = nullptr, evA = nullptr, evB = nullptr, evW = nullptr;
    if (s2 == nullptr) {
        cudaStreamCreateWithFlags(&s2, cudaStreamNonBlocking);
        cudaEventCreateWithFlags(&ev0, cudaEventDisableTiming);
        cudaEventCreateWithFlags(&evA, cudaEventDisableTiming);
        cudaEventCreateWithFlags(&evB, cudaEventDisableTiming);
        cudaEventCreateWithFlags(&evW, cudaEventDisableTiming);
        cudaFuncSetAttribute(gemm_fused_kernel,
                             cudaFuncAttributeMaxDynamicSharedMemorySize,
                             SM_GEMM_TOTAL);
    }

    // fork s2 from the captured origin stream BEFORE any s2 launch
    cudaEventRecord(ev0, 0);
    cudaStreamWaitEvent(s2, ev0, 0);

    // s2: weight split (runs concurrent with tangent_deg on main)
    prep_w_kernel<<<256, 256, 0, s2>>>(lin_w, conv_w);
    cudaEventRecord(evW, s2);

    // main: tangent + deg (g_deg is zero: static init / scan3 restore)
    tangent_deg_kernel<<<DEG_BLOCKS + TAN_BLOCKS, 256>>>(node, h1, h2, h3, curv, edst);

    // fork: CSR pipeline on s2 (after tangent_deg on main)
    cudaEventRecord(evA, 0);
    cudaStreamWaitEvent(s2, evA, 0);
    scan12_kernel<<<SCAN_BLOCKS, 1024, 0, s2>>>();
    scan3_kernel<<<SCAN_BLOCKS, 1024, 0, s2>>>();
    place_kernel<<<DEG_BLOCKS, 256, 0, s2>>>(esrc, edst);

    // main: GEMM (needs W from s2; wait resolves long before tangent ends)
    cudaStreamWaitEvent(0, evW, 0);
    gemm_fused_kernel<<<2 * G1_BLOCKS, 256, SM_GEMM_TOTAL>>>(lin_b, conv_b);

    // join
    cudaEventRecord(evB, s2);
    cudaStreamWaitEvent(0, evB, 0);
    finalize_kernel<<<(NN + 7) / 8, 256>>>(curv, out);
}

// round 14
// speedup vs baseline: 1.0099x; 1.0099x over previous
#include <cuda_runtime.h>
#include <cuda_bf16.h>
#include <cuda_fp16.h>
#include <cstdint>
#include <math.h>

#define NN 50000
#define DD 128
#define EE 625000
#define SCAN_BLOCKS 49                     // ceil(50000/1024)
#define DEG_BLOCKS ((EE + 255) / 256)      // 2442
#define TAN_BLOCKS ((4 * NN) / 8)          // 25000
#define G1_BLOCKS ((NN + 127) / 128)       // 391

// ---------------- scratch (static device allocations) ----------------------
__device__ __nv_bfloat16 g_A1hi[NN * DD];
__device__ __nv_bfloat16 g_A1lo[NN * DD];
__device__ __nv_bfloat16 g_A2hi[NN * 3 * DD];    // [n][k*128+i]
__device__ __nv_bfloat16 g_A2lo[NN * 3 * DD];
__device__ __nv_bfloat16 g_W1hi[DD * DD];
__device__ __nv_bfloat16 g_W1lo[DD * DD];
__device__ __nv_bfloat16 g_W2hi[DD * 3 * DD];    // [o][k*128+i]
__device__ __nv_bfloat16 g_W2lo[DD * 3 * DD];
__device__ __half g_transformed[NN * DD];        // fp16: gather-only consumer
__device__ float g_conv[NN * DD];
__device__ int   g_deg[NN];        // zero at load; scan3 restores zeros per run
__device__ int   g_rowstart[NN + 1];
__device__ int   g_cursor[NN];
__device__ int   g_csr[EE];
__device__ int   g_bsum[SCAN_BLOCKS];
__device__ int   g_boff[SCAN_BLOCKS];
__device__ int   g_ticket;         // zero at load; scan12 last block restores

#define SMEM_SWIZZLE_128B(b) ((b) ^ (((b) >> 3) & 0x70))

__device__ __forceinline__ uint32_t smem_to_u32(const void* p) {
    uint32_t a;
    asm("{ .reg .u64 t; cvta.to.shared.u64 t, %1; cvt.u32.u64 %0, t; }"
        : "=r"(a) : "l"(p));
    return a;
}
__device__ __forceinline__ void cp_async16(uint32_t saddr, const void* gptr) {
    asm volatile("cp.async.cg.shared.global [%0], [%1], 16;"
                 :: "r"(saddr), "l"(gptr) : "memory");
}
__device__ __forceinline__ void cp_commit() {
    asm volatile("cp.async.commit_group;" ::: "memory");
}
template <int N>
__device__ __forceinline__ void cp_wait() {
    asm volatile("cp.async.wait_group %0;" :: "n"(N) : "memory");
}
__device__ __forceinline__ void ldsm_x4(uint32_t* r, uint32_t addr) {
    asm volatile("ldmatrix.sync.aligned.m8n8.x4.shared.b16 {%0,%1,%2,%3}, [%4];"
                 : "=r"(r[0]), "=r"(r[1]), "=r"(r[2]), "=r"(r[3])
                 : "r"(addr));
}
__device__ __forceinline__ void mma_bf16(float* d, const uint32_t* a,
                                         const uint32_t* b) {
    asm volatile(
        "mma.sync.aligned.m16n8k16.row.col.f32.bf16.bf16.f32 "
        "{%0,%1,%2,%3}, {%4,%5,%6,%7}, {%8,%9}, {%0,%1,%2,%3};"
        : "+f"(d[0]), "+f"(d[1]), "+f"(d[2]), "+f"(d[3])
        : "r"(a[0]), "r"(a[1]), "r"(a[2]), "r"(a[3]), "r"(b[0]), "r"(b[1]));
}
__device__ __forceinline__ void split_bf16(float v, __nv_bfloat16& hi, __nv_bfloat16& lo) {
    hi = __float2bfloat16(v);
    lo = __float2bfloat16(v - __bfloat162float(hi));
}

// ---------------- K-W: weight split only (off critical path, on s2) ---------
__global__ void prep_w_kernel(const float* __restrict__ lin_w,
                              const float* __restrict__ conv_w) {
    int idx = blockIdx.x * blockDim.x + threadIdx.x;   // 0 .. 65535
    if (idx < DD * DD) {
        split_bf16(lin_w[idx], g_W1hi[idx], g_W1lo[idx]);
    } else if (idx < DD * DD + 3 * DD * DD) {
        int t = idx - DD * DD;          // target index in [o][k*128+i]
        int o = t / (3 * DD);
        int r = t - o * (3 * DD);
        int k = r >> 7, i = r & 127;
        split_bf16(conv_w[(o * DD + i) * 3 + k], g_W2hi[t], g_W2lo[t]);
    }
}

// ---------------- K2: fused deg-count + logmap0->bf16 hi/lo -----------------
// (g_deg is all-zero on entry: static init on first run, scan3 restore after)
__global__ void tangent_deg_kernel(const float* __restrict__ node,
                                   const float* __restrict__ h1,
                                   const float* __restrict__ h2,
                                   const float* __restrict__ h3,
                                   const float* __restrict__ curv,
                                   const int* __restrict__ edst) {
    if (blockIdx.x < DEG_BLOCKS) {
        int e = blockIdx.x * 256 + threadIdx.x;
        if (e < EE) atomicAdd(&g_deg[edst[e]], 1);
        return;
    }
    int rid  = ((blockIdx.x - DEG_BLOCKS) << 3) + (threadIdx.x >> 5);
    int lane = threadIdx.x & 31;
    if (rid >= 4 * NN) return;

    const float* srcp;
    int n = 0, k = 0;
    bool is_node = (rid < NN);
    if (is_node) {
        n = rid;
        srcp = node + (size_t)n * DD;
    } else {
        int t = rid - NN;
        k = t / NN;
        n = t - k * NN;
        const float* h = (k == 0) ? h1 : (k == 1) ? h2 : h3;
        srcp = h + (size_t)n * DD;
    }

    float4 x = ((const float4*)srcp)[lane];
    float ss = x.x * x.x + x.y * x.y + x.z * x.z + x.w * x.w;
#pragma unroll
    for (int off = 16; off; off >>= 1) ss += __shfl_xor_sync(0xffffffffu, ss, off);

    float c  = fabsf(curv[0]);
    float sc = sqrtf(c);
    float xn  = fmaxf(sqrtf(ss), 1e-15f);
    float arg = fminf(sc * xn, 1.0f - 1e-5f);
    float alpha = atanhf(arg) / (sc * xn);

    float v[4] = {x.x * alpha, x.y * alpha, x.z * alpha, x.w * alpha};
    union { __nv_bfloat16 b[4]; uint2 u; } ph, pl;
#pragma unroll
    for (int t = 0; t < 4; t++) split_bf16(v[t], ph.b[t], pl.b[t]);

    if (is_node) {
        ((uint2*)(g_A1hi + (size_t)n * DD))[lane] = ph.u;
        ((uint2*)(g_A1lo + (size_t)n * DD))[lane] = pl.u;
    } else {
        size_t off = (size_t)n * (3 * DD) + k * DD + lane * 4;
        *(uint2*)(g_A2hi + off) = ph.u;
        *(uint2*)(g_A2lo + off) = pl.u;
    }
}

// ---------------- K3: scan phase 1 + (last block, 1 warp) phase 2 -----------
__global__ __launch_bounds__(1024) void scan12_kernel() {
    __shared__ int wsum[32];
    __shared__ int s_last;
    int tid = threadIdx.x, lane = tid & 31, w = tid >> 5;
    int idx = blockIdx.x * 1024 + tid;
    int v = (idx < NN) ? g_deg[idx] : 0;
    int x = v;
#pragma unroll
    for (int off = 16; off; off >>= 1) x += __shfl_xor_sync(0xffffffffu, x, off);
    if (lane == 0) wsum[w] = x;
    __syncthreads();
    if (w == 0) {
        int z = wsum[lane];
#pragma unroll
        for (int off = 16; off; off >>= 1) z += __shfl_xor_sync(0xffffffffu, z, off);
        if (lane == 0) g_bsum[blockIdx.x] = z;
    }
    __threadfence();
    if (tid == 0) {
        int t = atomicAdd(&g_ticket, 1);
        s_last = (t == (int)gridDim.x - 1);
    }
    __syncthreads();
    if (s_last && w == 0) {
        int v0 = (lane < SCAN_BLOCKS) ? g_bsum[lane] : 0;
        int v1 = (lane + 32 < SCAN_BLOCKS) ? g_bsum[lane + 32] : 0;
        int x0 = v0, x1 = v1;
#pragma unroll
        for (int off = 1; off < 32; off <<= 1) {
            int y0 = __shfl_up_sync(0xffffffffu, x0, off);
            int y1 = __shfl_up_sync(0xffffffffu, x1, off);
            if (lane >= off) { x0 += y0; x1 += y1; }
        }
        int tot0 = __shfl_sync(0xffffffffu, x0, 31);
        x1 += tot0;
        g_boff[lane] = x0 - v0;
        if (lane + 32 < SCAN_BLOCKS) g_boff[lane + 32] = x1 - v1;
        if (lane == 0) { g_rowstart[0] = 0; g_ticket = 0; }   // restore for replay
    }
}

// ---------------- K4: block-local scan + offset; restores deg zeros ---------
__global__ __launch_bounds__(1024) void scan3_kernel() {
    __shared__ int wsum[32];
    int tid = threadIdx.x, lane = tid & 31, w = tid >> 5;
    int idx = blockIdx.x * 1024 + tid;
    int v = (idx < NN) ? g_deg[idx] : 0;
    int x = v;
#pragma unroll
    for (int off = 1; off < 32; off <<= 1) {
        int y = __shfl_up_sync(0xffffffffu, x, off);
        if (lane >= off) x += y;
    }
    if (lane == 31) wsum[w] = x;
    __syncthreads();
    if (w == 0) {
        int z = wsum[lane];
#pragma unroll
        for (int off = 1; off < 32; off <<= 1) {
            int y = __shfl_up_sync(0xffffffffu, z, off);
            if (lane >= off) z += y;
        }
        wsum[lane] = z;
    }
    __syncthreads();
    int incl = x + ((w > 0) ? wsum[w - 1] : 0) + g_boff[blockIdx.x];
    if (idx < NN) {
        g_rowstart[idx + 1] = incl;
        g_cursor[idx]       = incl - v;
        g_deg[idx]          = 0;       // restore zeros for next replay
    }
}

// ---------------- K5: place edges into CSR ----------------------------------
__global__ void place_kernel(const int* __restrict__ src,
                             const int* __restrict__ dst) {
    int e = blockIdx.x * blockDim.x + threadIdx.x;
    if (e < EE) {
        int d = dst[e];
        int p = atomicAdd(&g_cursor[d], 1);
        g_csr[p] = src[e];
    }
}

// ---------------- K6: fused HMMA GEMMs (R10 order: GEMM1 blocks first) -------
static constexpr int ST_AHI = 0;
static constexpr int ST_ALO = 16384;
static constexpr int ST_WHI = 32768;
static constexpr int ST_WLO = 49152;
static constexpr int ST_STRIDE = 65536;
static constexpr int SM_BIAS_OFF = 2 * ST_STRIDE;          // 131072
static constexpr int SM_GEMM_TOTAL = SM_BIAS_OFF + 512;    // 131584

template <int K, bool OUT_HALF>
__device__ __forceinline__ void gemm_body(
    int blk, char* smem, uint32_t sb,
    const __nv_bfloat16* Ahi, const __nv_bfloat16* Alo,
    const __nv_bfloat16* Whi, const __nv_bfloat16* Wlo,
    void* out_v, const float* bias) {
    constexpr int CH = K / 64;
    constexpr int KV = K / 8;

    int tid = threadIdx.x;
    int wid = tid >> 5;
    int lane = tid & 31;
    int warp_m = wid & 3;
    int warp_n = wid >> 2;
    int g  = lane >> 3;
    int ri = lane & 7;

    const uint4* A4hi = (const uint4*)Ahi;
    const uint4* A4lo = (const uint4*)Alo;
    const uint4* W4hi = (const uint4*)Whi;
    const uint4* W4lo = (const uint4*)Wlo;

    if (tid < 128) ((float*)(smem + SM_BIAS_OFF))[tid] = bias[tid];

    int base = blk * 128;

    auto prefetch = [&](int c, int buf) {
        uint32_t st = sb + buf * ST_STRIDE;
#pragma unroll
        for (int it = 0; it < 4; ++it) {
            int idx = tid + it * 256;
            int row = idx >> 3;
            int kq  = idx & 7;
            uint32_t off = SMEM_SWIZZLE_128B((uint32_t)(row * 128 + kq * 16));
            int gn = base + row;
            if (gn >= NN) gn = NN - 1;
            size_t gidx = (size_t)gn * KV + c * 8 + kq;
            size_t widx = (size_t)row * KV + c * 8 + kq;
            cp_async16(st + ST_AHI + off, A4hi + gidx);
            cp_async16(st + ST_ALO + off, A4lo + gidx);
            cp_async16(st + ST_WHI + off, W4hi + widx);
            cp_async16(st + ST_WLO + off, W4lo + widx);
        }
        cp_commit();
    };

    float acc[2][8][4];
#pragma unroll
    for (int mi = 0; mi < 2; mi++)
#pragma unroll
        for (int nb = 0; nb < 8; nb++)
#pragma unroll
            for (int q = 0; q < 4; q++) acc[mi][nb][q] = 0.f;

    prefetch(0, 0);

    for (int c = 0; c < CH; ++c) {
        if (c + 1 < CH) {
            prefetch(c + 1, (c + 1) & 1);
            cp_wait<1>();
        } else {
            cp_wait<0>();
        }
        __syncthreads();

        uint32_t st = sb + (c & 1) * ST_STRIDE;

#pragma unroll
        for (int ks = 0; ks < 4; ++ks) {
            uint32_t a_hi[2][4], a_lo[2][4];
#pragma unroll
            for (int mi = 0; mi < 2; ++mi) {
                int row = warp_m * 32 + mi * 16 + ((g & 1) << 3) + ri;
                int kb  = ks * 32 + ((g >> 1) << 4);
                uint32_t off = SMEM_SWIZZLE_128B((uint32_t)(row * 128 + kb));
                ldsm_x4(a_hi[mi], st + ST_AHI + off);
                ldsm_x4(a_lo[mi], st + ST_ALO + off);
            }
#pragma unroll
            for (int pp = 0; pp < 3; ++pp) {
                uint32_t woff = (pp == 1) ? (uint32_t)ST_WLO : (uint32_t)ST_WHI;
                uint32_t (*af)[4] = (pp == 2) ? a_lo : a_hi;
                uint32_t b[8][2];
#pragma unroll
                for (int nb2 = 0; nb2 < 4; ++nb2) {
                    int row = warp_n * 64 + nb2 * 16 + ((g >> 1) << 3) + ri;
                    int kb  = ks * 32 + ((g & 1) << 4);
                    uint32_t off = SMEM_SWIZZLE_128B((uint32_t)(row * 128 + kb));
                    uint32_t r[4];
                    ldsm_x4(r, st + woff + off);
                    b[nb2 * 2 + 0][0] = r[0];
                    b[nb2 * 2 + 0][1] = r[1];
                    b[nb2 * 2 + 1][0] = r[2];
                    b[nb2 * 2 + 1][1] = r[3];
                }
#pragma unroll
                for (int mi = 0; mi < 2; ++mi)
#pragma unroll
                    for (int nb = 0; nb < 8; ++nb)
                        mma_bf16(acc[mi][nb], af[mi], b[nb]);
            }
        }
        __syncthreads();
    }

    const float* bias_s = (const float*)(smem + SM_BIAS_OFF);
    int qrow = lane >> 2;
    int qcol = (lane & 3) * 2;
#pragma unroll
    for (int mi = 0; mi < 2; ++mi) {
#pragma unroll
        for (int nb = 0; nb < 8; ++nb) {
            int col = warp_n * 64 + nb * 8 + qcol;
            float b0 = bias_s[col], b1 = bias_s[col + 1];
            int r0 = base + warp_m * 32 + mi * 16 + qrow;
            int r1 = r0 + 8;
            if (OUT_HALF) {
                __half* out = (__half*)out_v;
                if (r0 < NN)
                    *(__half2*)(out + (size_t)r0 * DD + col) =
                        __floats2half2_rn(acc[mi][nb][0] + b0, acc[mi][nb][1] + b1);
                if (r1 < NN)
                    *(__half2*)(out + (size_t)r1 * DD + col) =
                        __floats2half2_rn(acc[mi][nb][2] + b0, acc[mi][nb][3] + b1);
            } else {
                float* out = (float*)out_v;
                if (r0 < NN)
                    *(float2*)(out + (size_t)r0 * DD + col) =
                        make_float2(acc[mi][nb][0] + b0, acc[mi][nb][1] + b1);
                if (r1 < NN)
                    *(float2*)(out + (size_t)r1 * DD + col) =
                        make_float2(acc[mi][nb][2] + b0, acc[mi][nb][3] + b1);
            }
        }
    }
}

__global__ __launch_bounds__(256)
void gemm_fused_kernel(const float* __restrict__ lin_b,
                       const float* __restrict__ conv_b) {
    extern __shared__ char smem[];
    uint32_t sb = smem_to_u32(smem);
    if (blockIdx.x < G1_BLOCKS) {
        gemm_body<128, true>(blockIdx.x, smem, sb, g_A1hi, g_A1lo, g_W1hi, g_W1lo,
                             g_transformed, lin_b);
    } else {
        gemm_body<384, false>(blockIdx.x - G1_BLOCKS, smem, sb, g_A2hi, g_A2lo,
                              g_W2hi, g_W2lo, g_conv, conv_b);
    }
}

// ---------------- K7: gather(fp16) + mean + conv add + expmap0 ---------------
__global__ void finalize_kernel(const float* __restrict__ curv,
                                float* __restrict__ out) {
    int n = (blockIdx.x * blockDim.x + threadIdx.x) >> 5;
    int lane = threadIdx.x & 31;
    if (n >= NN) return;

    int s = g_rowstart[n];
    int e = g_rowstart[n + 1];
    const uint2* T = (const uint2*)g_transformed;   // 4 halves per lane

    float4 a = make_float4(0.f, 0.f, 0.f, 0.f);
    int p = s;
    for (; p + 4 <= e; p += 4) {
        int i0 = g_csr[p + 0], i1 = g_csr[p + 1];
        int i2 = g_csr[p + 2], i3 = g_csr[p + 3];
        uint2 u0 = T[i0 * 32 + lane];
        uint2 u1 = T[i1 * 32 + lane];
        uint2 u2 = T[i2 * 32 + lane];
        uint2 u3 = T[i3 * 32 + lane];
        __half2 h;
        float2 f;
#define ACC_U(u) \
        h = *(__half2*)&(u).x; f = __half22float2(h); a.x += f.x; a.y += f.y; \
        h = *(__half2*)&(u).y; f = __half22float2(h); a.z += f.x; a.w += f.y;
        ACC_U(u0) ACC_U(u1) ACC_U(u2) ACC_U(u3)
    }
    for (; p < e; ++p) {
        int i0 = g_csr[p];
        uint2 u0 = T[i0 * 32 + lane];
        __half2 h;
        float2 f;
        ACC_U(u0)
#undef ACC_U
    }

    float inv = (e > s) ? 1.0f / (float)(e - s) : 0.0f;
    float4 cv = ((const float4*)g_conv)[n * 32 + lane];
    float4 v = make_float4(cv.x + a.x * inv, cv.y + a.y * inv,
                           cv.z + a.z * inv, cv.w + a.w * inv);

    float ss = v.x * v.x + v.y * v.y + v.z * v.z + v.w * v.w;
#pragma unroll
    for (int off = 16; off; off >>= 1) ss += __shfl_xor_sync(0xffffffffu, ss, off);

    float c  = fabsf(curv[0]);
    float sc = sqrtf(c);
    float un = fmaxf(sqrtf(ss), 1e-15f);
    float arg = sc * un;
    float f2 = tanhf(arg) / arg;

    ((float4*)out)[n * 32 + lane] =
        make_float4(v.x * f2, v.y * f2, v.z * f2, v.w * f2);
}

// ---------------- launch: R10 topology + prep on s2 --------------------------
extern "C" void kernel_launch(void* const* d_in, const int* in_sizes, int n_in,
                              void* d_out, int out_size) {
    const float* node   = (const float*)d_in[0];
    const float* h1     = (const float*)d_in[1];
    const float* h2     = (const float*)d_in[2];
    const float* h3     = (const float*)d_in[3];
    const float* lin_w  = (const float*)d_in[4];
    const float* lin_b  = (const float*)d_in[5];
    const float* conv_w = (const float*)d_in[6];
    const float* conv_b = (const float*)d_in[7];
    const float* curv   = (const float*)d_in[8];
    const int*   esrc   = (const int*)d_in[9];
    const int*   edst   = (const int*)d_in[10];
    float* out = (float*)d_out;

    static cudaStream_t s2 = nullptr;
    static cudaEvent_t ev0 = nullptr, evA = nullptr, evB = nullptr, evW = nullptr;
    if (s2 == nullptr) {
        cudaStreamCreateWithFlags(&s2, cudaStreamNonBlocking);
        cudaEventCreateWithFlags(&ev0, cudaEventDisableTiming);
        cudaEventCreateWithFlags(&evA, cudaEventDisableTiming);
        cudaEventCreateWithFlags(&evB, cudaEventDisableTiming);
        cudaEventCreateWithFlags(&evW, cudaEventDisableTiming);
        cudaFuncSetAttribute(gemm_fused_kernel,
                             cudaFuncAttributeMaxDynamicSharedMemorySize,
                             SM_GEMM_TOTAL);
    }

    // fork s2 from the captured origin stream BEFORE any s2 launch
    cudaEventRecord(ev0, 0);
    cudaStreamWaitEvent(s2, ev0, 0);

    // s2: weight split (runs concurrent with tangent_deg on main)
    prep_w_kernel<<<256, 256, 0, s2>>>(lin_w, conv_w);
    cudaEventRecord(evW, s2);

    // main: tangent + deg (g_deg is zero: static init / scan3 restore)
    tangent_deg_kernel<<<DEG_BLOCKS + TAN_BLOCKS, 256>>>(node, h1, h2, h3, curv, edst);

    // fork: CSR pipeline on s2 (after tangent_deg on main)
    cudaEventRecord(evA, 0);
    cudaStreamWaitEvent(s2, evA, 0);
    scan12_kernel<<<SCAN_BLOCKS, 1024, 0, s2>>>();
    scan3_kernel<<<SCAN_BLOCKS, 1024, 0, s2>>>();
    place_kernel<<<DEG_BLOCKS, 256, 0, s2>>>(esrc, edst);

    // main: GEMM (R10 ordering: GEMM1 blocks first)
    cudaStreamWaitEvent(0, evW, 0);
    gemm_fused_kernel<<<2 * G1_BLOCKS, 256, SM_GEMM_TOTAL>>>(lin_b, conv_b);

    // join
    cudaEventRecord(evB, s2);
    cudaStreamWaitEvent(0, evB, 0);
    finalize_kernel<<<(NN + 7) / 8, 256>>>(curv, out);
}

// round 15
// speedup vs baseline: 1.2258x; 1.2138x over previous
#include <cuda_runtime.h>
#include <cuda_bf16.h>
#include <cuda_fp16.h>
#include <cstdint>
#include <math.h>

#define NN 50000
#define DD 128
#define EE 625000
#define SCAN_BLOCKS 49                     // ceil(50000/1024)
#define DEG_BLOCKS ((EE + 255) / 256)      // 2442
#define TAN_BLOCKS ((4 * NN) / 8)          // 25000
#define G1_BLOCKS ((NN + 127) / 128)       // 391

// ---------------- scratch (static device allocations) ----------------------
__device__ __half g_A1[NN * DD];                 // logmap0(node), fp16
__device__ __half g_A2[NN * 3 * DD];             // th packed [n][k*128+i], fp16
__device__ __half g_W1hi[DD * DD];               // lin_w fp16 hi
__device__ __half g_W1lo[DD * DD];               // lin_w fp16 lo (residual)
__device__ __half g_W2hi[DD * 3 * DD];           // conv_w packed [o][k*128+i]
__device__ __half g_W2lo[DD * 3 * DD];
__device__ __half g_transformed[NN * DD];        // fp16: gather-only consumer
__device__ float g_conv[NN * DD];
__device__ int   g_deg[NN];
__device__ int   g_rowstart[NN + 1];
__device__ int   g_cursor[NN];
__device__ int   g_csr[EE];
__device__ int   g_bsum[SCAN_BLOCKS];
__device__ int   g_boff[SCAN_BLOCKS];
__device__ int   g_ticket;

#define SMEM_SWIZZLE_128B(b) ((b) ^ (((b) >> 3) & 0x70))

__device__ __forceinline__ uint32_t smem_to_u32(const void* p) {
    uint32_t a;
    asm("{ .reg .u64 t; cvta.to.shared.u64 t, %1; cvt.u32.u64 %0, t; }"
        : "=r"(a) : "l"(p));
    return a;
}
__device__ __forceinline__ void cp_async16(uint32_t saddr, const void* gptr) {
    asm volatile("cp.async.cg.shared.global [%0], [%1], 16;"
                 :: "r"(saddr), "l"(gptr) : "memory");
}
__device__ __forceinline__ void cp_commit() {
    asm volatile("cp.async.commit_group;" ::: "memory");
}
template <int N>
__device__ __forceinline__ void cp_wait() {
    asm volatile("cp.async.wait_group %0;" :: "n"(N) : "memory");
}
__device__ __forceinline__ void ldsm_x4(uint32_t* r, uint32_t addr) {
    asm volatile("ldmatrix.sync.aligned.m8n8.x4.shared.b16 {%0,%1,%2,%3}, [%4];"
                 : "=r"(r[0]), "=r"(r[1]), "=r"(r[2]), "=r"(r[3])
                 : "r"(addr));
}
__device__ __forceinline__ void mma_f16(float* d, const uint32_t* a,
                                        const uint32_t* b) {
    asm volatile(
        "mma.sync.aligned.m16n8k16.row.col.f32.f16.f16.f32 "
        "{%0,%1,%2,%3}, {%4,%5,%6,%7}, {%8,%9}, {%0,%1,%2,%3};"
        : "+f"(d[0]), "+f"(d[1]), "+f"(d[2]), "+f"(d[3])
        : "r"(a[0]), "r"(a[1]), "r"(a[2]), "r"(a[3]), "r"(b[0]), "r"(b[1]));
}
__device__ __forceinline__ void split_fp16(float v, __half& hi, __half& lo) {
    hi = __float2half(v);
    lo = __float2half(v - __half2float(hi));
}

// ---------------- K1: prep (zero deg/ticket + pack/split weights) -----------
__global__ void prep_kernel(const float* __restrict__ lin_w,
                            const float* __restrict__ conv_w) {
    int idx = blockIdx.x * blockDim.x + threadIdx.x;   // 0 .. 65535
    if (idx == 0) g_ticket = 0;
    if (idx < NN) g_deg[idx] = 0;
    if (idx < DD * DD) {
        split_fp16(lin_w[idx], g_W1hi[idx], g_W1lo[idx]);
    } else if (idx < DD * DD + 3 * DD * DD) {
        int t = idx - DD * DD;          // target index in [o][k*128+i]
        int o = t / (3 * DD);
        int r = t - o * (3 * DD);
        int k = r >> 7, i = r & 127;
        split_fp16(conv_w[(o * DD + i) * 3 + k], g_W2hi[t], g_W2lo[t]);
    }
}

// ---------------- K2: fused deg-count + logmap0->fp16 -----------------------
__global__ void tangent_deg_kernel(const float* __restrict__ node,
                                   const float* __restrict__ h1,
                                   const float* __restrict__ h2,
                                   const float* __restrict__ h3,
                                   const float* __restrict__ curv,
                                   const int* __restrict__ edst) {
    if (blockIdx.x < DEG_BLOCKS) {
        int e = blockIdx.x * 256 + threadIdx.x;
        if (e < EE) atomicAdd(&g_deg[edst[e]], 1);
        return;
    }
    int rid  = ((blockIdx.x - DEG_BLOCKS) << 3) + (threadIdx.x >> 5);
    int lane = threadIdx.x & 31;
    if (rid >= 4 * NN) return;

    const float* srcp;
    int n = 0, k = 0;
    bool is_node = (rid < NN);
    if (is_node) {
        n = rid;
        srcp = node + (size_t)n * DD;
    } else {
        int t = rid - NN;
        k = t / NN;
        n = t - k * NN;
        const float* h = (k == 0) ? h1 : (k == 1) ? h2 : h3;
        srcp = h + (size_t)n * DD;
    }

    float4 x = ((const float4*)srcp)[lane];
    float ss = x.x * x.x + x.y * x.y + x.z * x.z + x.w * x.w;
#pragma unroll
    for (int off = 16; off; off >>= 1) ss += __shfl_xor_sync(0xffffffffu, ss, off);

    float c  = fabsf(curv[0]);
    float sc = sqrtf(c);
    float xn  = fmaxf(sqrtf(ss), 1e-15f);
    float arg = fminf(sc * xn, 1.0f - 1e-5f);
    float alpha = atanhf(arg) / (sc * xn);

    union { __half b[4]; uint2 u; } ph;
    ph.b[0] = __float2half(x.x * alpha);
    ph.b[1] = __float2half(x.y * alpha);
    ph.b[2] = __float2half(x.z * alpha);
    ph.b[3] = __float2half(x.w * alpha);

    if (is_node) {
        ((uint2*)(g_A1 + (size_t)n * DD))[lane] = ph.u;
    } else {
        size_t off = (size_t)n * (3 * DD) + k * DD + lane * 4;
        *(uint2*)(g_A2 + off) = ph.u;
    }
}

// ---------------- K3: scan phase 1 + (last block, 1 warp) phase 2 -----------
__global__ __launch_bounds__(1024) void scan12_kernel() {
    __shared__ int wsum[32];
    __shared__ int s_last;
    int tid = threadIdx.x, lane = tid & 31, w = tid >> 5;
    int idx = blockIdx.x * 1024 + tid;
    int v = (idx < NN) ? g_deg[idx] : 0;
    int x = v;
#pragma unroll
    for (int off = 16; off; off >>= 1) x += __shfl_xor_sync(0xffffffffu, x, off);
    if (lane == 0) wsum[w] = x;
    __syncthreads();
    if (w == 0) {
        int z = wsum[lane];
#pragma unroll
        for (int off = 16; off; off >>= 1) z += __shfl_xor_sync(0xffffffffu, z, off);
        if (lane == 0) g_bsum[blockIdx.x] = z;
    }
    __threadfence();
    if (tid == 0) {
        int t = atomicAdd(&g_ticket, 1);
        s_last = (t == (int)gridDim.x - 1);
    }
    __syncthreads();
    if (s_last && w == 0) {
        int v0 = (lane < SCAN_BLOCKS) ? g_bsum[lane] : 0;
        int v1 = (lane + 32 < SCAN_BLOCKS) ? g_bsum[lane + 32] : 0;
        int x0 = v0, x1 = v1;
#pragma unroll
        for (int off = 1; off < 32; off <<= 1) {
            int y0 = __shfl_up_sync(0xffffffffu, x0, off);
            int y1 = __shfl_up_sync(0xffffffffu, x1, off);
            if (lane >= off) { x0 += y0; x1 += y1; }
        }
        int tot0 = __shfl_sync(0xffffffffu, x0, 31);
        x1 += tot0;
        g_boff[lane] = x0 - v0;
        if (lane + 32 < SCAN_BLOCKS) g_boff[lane + 32] = x1 - v1;
        if (lane == 0) g_rowstart[0] = 0;
    }
}

// ---------------- K4: block-local scan + offset -> rowstart / cursor --------
__global__ __launch_bounds__(1024) void scan3_kernel() {
    __shared__ int wsum[32];
    int tid = threadIdx.x, lane = tid & 31, w = tid >> 5;
    int idx = blockIdx.x * 1024 + tid;
    int v = (idx < NN) ? g_deg[idx] : 0;
    int x = v;
#pragma unroll
    for (int off = 1; off < 32; off <<= 1) {
        int y = __shfl_up_sync(0xffffffffu, x, off);
        if (lane >= off) x += y;
    }
    if (lane == 31) wsum[w] = x;
    __syncthreads();
    if (w == 0) {
        int z = wsum[lane];
#pragma unroll
        for (int off = 1; off < 32; off <<= 1) {
            int y = __shfl_up_sync(0xffffffffu, z, off);
            if (lane >= off) z += y;
        }
        wsum[lane] = z;
    }
    __syncthreads();
    int incl = x + ((w > 0) ? wsum[w - 1] : 0) + g_boff[blockIdx.x];
    if (idx < NN) {
        g_rowstart[idx + 1] = incl;
        g_cursor[idx]       = incl - v;
    }
}

// ---------------- K5: place edges into CSR ----------------------------------
__global__ void place_kernel(const int* __restrict__ src,
                             const int* __restrict__ dst) {
    int e = blockIdx.x * blockDim.x + threadIdx.x;
    if (e < EE) {
        int d = dst[e];
        int p = atomicAdd(&g_cursor[d], 1);
        g_csr[p] = src[e];
    }
}

// ---------------- K6: fused HMMA GEMMs, fp16 2-pass (AhiWhi + AhiWlo) --------
static constexpr int ST_A   = 0;
static constexpr int ST_WHI = 16384;
static constexpr int ST_WLO = 32768;
static constexpr int ST_STRIDE = 49152;
static constexpr int SM_BIAS_OFF = 2 * ST_STRIDE;          // 98304
static constexpr int SM_GEMM_TOTAL = SM_BIAS_OFF + 512;    // 98816

template <int K, bool OUT_HALF>
__device__ __forceinline__ void gemm_body(
    int blk, char* smem, uint32_t sb,
    const __half* A, const __half* Whi, const __half* Wlo,
    void* out_v, const float* bias) {
    constexpr int CH = K / 64;
    constexpr int KV = K / 8;

    int tid = threadIdx.x;
    int wid = tid >> 5;
    int lane = tid & 31;
    int warp_m = wid & 3;
    int warp_n = wid >> 2;
    int g  = lane >> 3;
    int ri = lane & 7;

    const uint4* A4   = (const uint4*)A;
    const uint4* W4hi = (const uint4*)Whi;
    const uint4* W4lo = (const uint4*)Wlo;

    if (tid < 128) ((float*)(smem + SM_BIAS_OFF))[tid] = bias[tid];

    int base = blk * 128;

    auto prefetch = [&](int c, int buf) {
        uint32_t st = sb + buf * ST_STRIDE;
#pragma unroll
        for (int it = 0; it < 4; ++it) {
            int idx = tid + it * 256;
            int row = idx >> 3;
            int kq  = idx & 7;
            uint32_t off = SMEM_SWIZZLE_128B((uint32_t)(row * 128 + kq * 16));
            int gn = base + row;
            if (gn >= NN) gn = NN - 1;
            size_t gidx = (size_t)gn * KV + c * 8 + kq;
            size_t widx = (size_t)row * KV + c * 8 + kq;
            cp_async16(st + ST_A + off, A4 + gidx);
            cp_async16(st + ST_WHI + off, W4hi + widx);
            cp_async16(st + ST_WLO + off, W4lo + widx);
        }
        cp_commit();
    };

    float acc[2][8][4];
#pragma unroll
    for (int mi = 0; mi < 2; mi++)
#pragma unroll
        for (int nb = 0; nb < 8; nb++)
#pragma unroll
            for (int q = 0; q < 4; q++) acc[mi][nb][q] = 0.f;

    prefetch(0, 0);

    for (int c = 0; c < CH; ++c) {
        if (c + 1 < CH) {
            prefetch(c + 1, (c + 1) & 1);
            cp_wait<1>();
        } else {
            cp_wait<0>();
        }
        __syncthreads();

        uint32_t st = sb + (c & 1) * ST_STRIDE;

#pragma unroll
        for (int ks = 0; ks < 4; ++ks) {
            uint32_t a_f[2][4];
#pragma unroll
            for (int mi = 0; mi < 2; ++mi) {
                int row = warp_m * 32 + mi * 16 + ((g & 1) << 3) + ri;
                int kb  = ks * 32 + ((g >> 1) << 4);
                uint32_t off = SMEM_SWIZZLE_128B((uint32_t)(row * 128 + kb));
                ldsm_x4(a_f[mi], st + ST_A + off);
            }
#pragma unroll
            for (int pp = 0; pp < 2; ++pp) {
                uint32_t woff = (pp == 1) ? (uint32_t)ST_WLO : (uint32_t)ST_WHI;
                uint32_t b[8][2];
#pragma unroll
                for (int nb2 = 0; nb2 < 4; ++nb2) {
                    int row = warp_n * 64 + nb2 * 16 + ((g >> 1) << 3) + ri;
                    int kb  = ks * 32 + ((g & 1) << 4);
                    uint32_t off = SMEM_SWIZZLE_128B((uint32_t)(row * 128 + kb));
                    uint32_t r[4];
                    ldsm_x4(r, st + woff + off);
                    b[nb2 * 2 + 0][0] = r[0];
                    b[nb2 * 2 + 0][1] = r[1];
                    b[nb2 * 2 + 1][0] = r[2];
                    b[nb2 * 2 + 1][1] = r[3];
                }
#pragma unroll
                for (int mi = 0; mi < 2; ++mi)
#pragma unroll
                    for (int nb = 0; nb < 8; ++nb)
                        mma_f16(acc[mi][nb], a_f[mi], b[nb]);
            }
        }
        __syncthreads();
    }

    const float* bias_s = (const float*)(smem + SM_BIAS_OFF);
    int qrow = lane >> 2;
    int qcol = (lane & 3) * 2;
#pragma unroll
    for (int mi = 0; mi < 2; ++mi) {
#pragma unroll
        for (int nb = 0; nb < 8; ++nb) {
            int col = warp_n * 64 + nb * 8 + qcol;
            float b0 = bias_s[col], b1 = bias_s[col + 1];
            int r0 = base + warp_m * 32 + mi * 16 + qrow;
            int r1 = r0 + 8;
            if (OUT_HALF) {
                __half* out = (__half*)out_v;
                if (r0 < NN)
                    *(__half2*)(out + (size_t)r0 * DD + col) =
                        __floats2half2_rn(acc[mi][nb][0] + b0, acc[mi][nb][1] + b1);
                if (r1 < NN)
                    *(__half2*)(out + (size_t)r1 * DD + col) =
                        __floats2half2_rn(acc[mi][nb][2] + b0, acc[mi][nb][3] + b1);
            } else {
                float* out = (float*)out_v;
                if (r0 < NN)
                    *(float2*)(out + (size_t)r0 * DD + col) =
                        make_float2(acc[mi][nb][0] + b0, acc[mi][nb][1] + b1);
                if (r1 < NN)
                    *(float2*)(out + (size_t)r1 * DD + col) =
                        make_float2(acc[mi][nb][2] + b0, acc[mi][nb][3] + b1);
            }
        }
    }
}

__global__ __launch_bounds__(256)
void gemm_fused_kernel(const float* __restrict__ lin_b,
                       const float* __restrict__ conv_b) {
    extern __shared__ char smem[];
    uint32_t sb = smem_to_u32(smem);
    if (blockIdx.x < G1_BLOCKS) {
        gemm_body<128, true>(blockIdx.x, smem, sb, g_A1, g_W1hi, g_W1lo,
                             g_transformed, lin_b);
    } else {
        gemm_body<384, false>(blockIdx.x - G1_BLOCKS, smem, sb, g_A2,
                              g_W2hi, g_W2lo, g_conv, conv_b);
    }
}

// ---------------- K7: gather(fp16) + mean + conv add + expmap0 ---------------
__global__ void finalize_kernel(const float* __restrict__ curv,
                                float* __restrict__ out) {
    int n = (blockIdx.x * blockDim.x + threadIdx.x) >> 5;
    int lane = threadIdx.x & 31;
    if (n >= NN) return;

    int s = g_rowstart[n];
    int e = g_rowstart[n + 1];
    const uint2* T = (const uint2*)g_transformed;   // 4 halves per lane

    float4 a = make_float4(0.f, 0.f, 0.f, 0.f);
    int p = s;
    for (; p + 4 <= e; p += 4) {
        int i0 = g_csr[p + 0], i1 = g_csr[p + 1];
        int i2 = g_csr[p + 2], i3 = g_csr[p + 3];
        uint2 u0 = T[i0 * 32 + lane];
        uint2 u1 = T[i1 * 32 + lane];
        uint2 u2 = T[i2 * 32 + lane];
        uint2 u3 = T[i3 * 32 + lane];
        __half2 h;
        float2 f;
#define ACC_U(u) \
        h = *(__half2*)&(u).x; f = __half22float2(h); a.x += f.x; a.y += f.y; \
        h = *(__half2*)&(u).y; f = __half22float2(h); a.z += f.x; a.w += f.y;
        ACC_U(u0) ACC_U(u1) ACC_U(u2) ACC_U(u3)
    }
    for (; p < e; ++p) {
        int i0 = g_csr[p];
        uint2 u0 = T[i0 * 32 + lane];
        __half2 h;
        float2 f;
        ACC_U(u0)
#undef ACC_U
    }

    float inv = (e > s) ? 1.0f / (float)(e - s) : 0.0f;
    float4 cv = ((const float4*)g_conv)[n * 32 + lane];
    float4 v = make_float4(cv.x + a.x * inv, cv.y + a.y * inv,
                           cv.z + a.z * inv, cv.w + a.w * inv);

    float ss = v.x * v.x + v.y * v.y + v.z * v.z + v.w * v.w;
#pragma unroll
    for (int off = 16; off; off >>= 1) ss += __shfl_xor_sync(0xffffffffu, ss, off);

    float c  = fabsf(curv[0]);
    float sc = sqrtf(c);
    float un = fmaxf(sqrtf(ss), 1e-15f);
    float arg = sc * un;
    float f2 = tanhf(arg) / arg;

    ((float4*)out)[n * 32 + lane] =
        make_float4(v.x * f2, v.y * f2, v.z * f2, v.w * f2);
}

// ---------------- launch: EXACT R10 topology ---------------------------------
extern "C" void kernel_launch(void* const* d_in, const int* in_sizes, int n_in,
                              void* d_out, int out_size) {
    const float* node   = (const float*)d_in[0];
    const float* h1     = (const float*)d_in[1];
    const float* h2     = (const float*)d_in[2];
    const float* h3     = (const float*)d_in[3];
    const float* lin_w  = (const float*)d_in[4];
    const float* lin_b  = (const float*)d_in[5];
    const float* conv_w = (const float*)d_in[6];
    const float* conv_b = (const float*)d_in[7];
    const float* curv   = (const float*)d_in[8];
    const int*   esrc   = (const int*)d_in[9];
    const int*   edst   = (const int*)d_in[10];
    float* out = (float*)d_out;

    static cudaStream_t s2 = nullptr;
    static cudaEvent_t evA = nullptr, evB = nullptr;
    if (s2 == nullptr) {
        cudaStreamCreateWithFlags(&s2, cudaStreamNonBlocking);
        cudaEventCreateWithFlags(&evA, cudaEventDisableTiming);
        cudaEventCreateWithFlags(&evB, cudaEventDisableTiming);
        cudaFuncSetAttribute(gemm_fused_kernel,
                             cudaFuncAttributeMaxDynamicSharedMemorySize,
                             SM_GEMM_TOTAL);
    }

    prep_kernel<<<(DD * DD + 3 * DD * DD + 255) / 256, 256>>>(lin_w, conv_w);
    tangent_deg_kernel<<<DEG_BLOCKS + TAN_BLOCKS, 256>>>(node, h1, h2, h3, curv, edst);

    // fork: CSR pipeline on s2, GEMM on main stream
    cudaEventRecord(evA, 0);
    cudaStreamWaitEvent(s2, evA, 0);

    scan12_kernel<<<SCAN_BLOCKS, 1024, 0, s2>>>();
    scan3_kernel<<<SCAN_BLOCKS, 1024, 0, s2>>>();
    place_kernel<<<DEG_BLOCKS, 256, 0, s2>>>(esrc, edst);

    gemm_fused_kernel<<<2 * G1_BLOCKS, 256, SM_GEMM_TOTAL>>>(lin_b, conv_b);

    // join
    cudaEventRecord(evB, s2);
    cudaStreamWaitEvent(0, evB, 0);

    finalize_kernel<<<(NN + 7) / 8, 256>>>(curv, out);
}

// round 16
// speedup vs baseline: 1.4842x; 1.2108x over previous
#include <cuda_runtime.h>
#include <cuda_bf16.h>
#include <cuda_fp16.h>
#include <cstdint>
#include <math.h>

#define NN 50000
#define DD 128
#define EE 625000
#define SCAN_BLOCKS 49                     // ceil(50000/1024)
#define DEG_BLOCKS ((EE + 255) / 256)      // 2442
#define TAN_BLOCKS ((4 * NN) / 8)          // 25000
#define G1_BLOCKS ((NN + 127) / 128)       // 391

// ---------------- scratch (static device allocations) ----------------------
__device__ __half g_A1[NN * DD];                 // logmap0(node), fp16
__device__ __half g_A2[NN * 3 * DD];             // th packed [n][k*128+i], fp16
__device__ __half g_W1[DD * DD];                 // lin_w fp16
__device__ __half g_W2[DD * 3 * DD];             // conv_w packed [o][k*128+i]
__device__ __half g_transformed[NN * DD];        // fp16: gather-only consumer
__device__ float g_conv[NN * DD];
__device__ int   g_deg[NN];
__device__ int   g_rowstart[NN + 1];
__device__ int   g_cursor[NN];
__device__ int   g_csr[EE];
__device__ int   g_bsum[SCAN_BLOCKS];
__device__ int   g_boff[SCAN_BLOCKS];
__device__ int   g_ticket;

#define SMEM_SWIZZLE_128B(b) ((b) ^ (((b) >> 3) & 0x70))

__device__ __forceinline__ uint32_t smem_to_u32(const void* p) {
    uint32_t a;
    asm("{ .reg .u64 t; cvta.to.shared.u64 t, %1; cvt.u32.u64 %0, t; }"
        : "=r"(a) : "l"(p));
    return a;
}
__device__ __forceinline__ void cp_async16(uint32_t saddr, const void* gptr) {
    asm volatile("cp.async.cg.shared.global [%0], [%1], 16;"
                 :: "r"(saddr), "l"(gptr) : "memory");
}
__device__ __forceinline__ void cp_commit() {
    asm volatile("cp.async.commit_group;" ::: "memory");
}
template <int N>
__device__ __forceinline__ void cp_wait() {
    asm volatile("cp.async.wait_group %0;" :: "n"(N) : "memory");
}
__device__ __forceinline__ void ldsm_x4(uint32_t* r, uint32_t addr) {
    asm volatile("ldmatrix.sync.aligned.m8n8.x4.shared.b16 {%0,%1,%2,%3}, [%4];"
                 : "=r"(r[0]), "=r"(r[1]), "=r"(r[2]), "=r"(r[3])
                 : "r"(addr));
}
__device__ __forceinline__ void mma_f16(float* d, const uint32_t* a,
                                        const uint32_t* b) {
    asm volatile(
        "mma.sync.aligned.m16n8k16.row.col.f32.f16.f16.f32 "
        "{%0,%1,%2,%3}, {%4,%5,%6,%7}, {%8,%9}, {%0,%1,%2,%3};"
        : "+f"(d[0]), "+f"(d[1]), "+f"(d[2]), "+f"(d[3])
        : "r"(a[0]), "r"(a[1]), "r"(a[2]), "r"(a[3]), "r"(b[0]), "r"(b[1]));
}

// ---------------- K1: prep (zero deg/ticket + pack weights fp16) ------------
__global__ void prep_kernel(const float* __restrict__ lin_w,
                            const float* __restrict__ conv_w) {
    int idx = blockIdx.x * blockDim.x + threadIdx.x;   // 0 .. 65535
    if (idx == 0) g_ticket = 0;
    if (idx < NN) g_deg[idx] = 0;
    if (idx < DD * DD) {
        g_W1[idx] = __float2half(lin_w[idx]);
    } else if (idx < DD * DD + 3 * DD * DD) {
        int t = idx - DD * DD;          // target index in [o][k*128+i]
        int o = t / (3 * DD);
        int r = t - o * (3 * DD);
        int k = r >> 7, i = r & 127;
        g_W2[t] = __float2half(conv_w[(o * DD + i) * 3 + k]);
    }
}

// ---------------- K2: fused deg-count + logmap0->fp16 -----------------------
__global__ void tangent_deg_kernel(const float* __restrict__ node,
                                   const float* __restrict__ h1,
                                   const float* __restrict__ h2,
                                   const float* __restrict__ h3,
                                   const float* __restrict__ curv,
                                   const int* __restrict__ edst) {
    if (blockIdx.x < DEG_BLOCKS) {
        int e = blockIdx.x * 256 + threadIdx.x;
        if (e < EE) atomicAdd(&g_deg[edst[e]], 1);
        return;
    }
    int rid  = ((blockIdx.x - DEG_BLOCKS) << 3) + (threadIdx.x >> 5);
    int lane = threadIdx.x & 31;
    if (rid >= 4 * NN) return;

    const float* srcp;
    int n = 0, k = 0;
    bool is_node = (rid < NN);
    if (is_node) {
        n = rid;
        srcp = node + (size_t)n * DD;
    } else {
        int t = rid - NN;
        k = t / NN;
        n = t - k * NN;
        const float* h = (k == 0) ? h1 : (k == 1) ? h2 : h3;
        srcp = h + (size_t)n * DD;
    }

    float4 x = ((const float4*)srcp)[lane];
    float ss = x.x * x.x + x.y * x.y + x.z * x.z + x.w * x.w;
#pragma unroll
    for (int off = 16; off; off >>= 1) ss += __shfl_xor_sync(0xffffffffu, ss, off);

    float c  = fabsf(curv[0]);
    float sc = sqrtf(c);
    float xn  = fmaxf(sqrtf(ss), 1e-15f);
    float arg = fminf(sc * xn, 1.0f - 1e-5f);
    float alpha = atanhf(arg) / (sc * xn);

    union { __half b[4]; uint2 u; } ph;
    ph.b[0] = __float2half(x.x * alpha);
    ph.b[1] = __float2half(x.y * alpha);
    ph.b[2] = __float2half(x.z * alpha);
    ph.b[3] = __float2half(x.w * alpha);

    if (is_node) {
        ((uint2*)(g_A1 + (size_t)n * DD))[lane] = ph.u;
    } else {
        size_t off = (size_t)n * (3 * DD) + k * DD + lane * 4;
        *(uint2*)(g_A2 + off) = ph.u;
    }
}

// ---------------- K3: scan phase 1 + (last block, 1 warp) phase 2 -----------
__global__ __launch_bounds__(1024) void scan12_kernel() {
    __shared__ int wsum[32];
    __shared__ int s_last;
    int tid = threadIdx.x, lane = tid & 31, w = tid >> 5;
    int idx = blockIdx.x * 1024 + tid;
    int v = (idx < NN) ? g_deg[idx] : 0;
    int x = v;
#pragma unroll
    for (int off = 16; off; off >>= 1) x += __shfl_xor_sync(0xffffffffu, x, off);
    if (lane == 0) wsum[w] = x;
    __syncthreads();
    if (w == 0) {
        int z = wsum[lane];
#pragma unroll
        for (int off = 16; off; off >>= 1) z += __shfl_xor_sync(0xffffffffu, z, off);
        if (lane == 0) g_bsum[blockIdx.x] = z;
    }
    __threadfence();
    if (tid == 0) {
        int t = atomicAdd(&g_ticket, 1);
        s_last = (t == (int)gridDim.x - 1);
    }
    __syncthreads();
    if (s_last && w == 0) {
        int v0 = (lane < SCAN_BLOCKS) ? g_bsum[lane] : 0;
        int v1 = (lane + 32 < SCAN_BLOCKS) ? g_bsum[lane + 32] : 0;
        int x0 = v0, x1 = v1;
#pragma unroll
        for (int off = 1; off < 32; off <<= 1) {
            int y0 = __shfl_up_sync(0xffffffffu, x0, off);
            int y1 = __shfl_up_sync(0xffffffffu, x1, off);
            if (lane >= off) { x0 += y0; x1 += y1; }
        }
        int tot0 = __shfl_sync(0xffffffffu, x0, 31);
        x1 += tot0;
        g_boff[lane] = x0 - v0;
        if (lane + 32 < SCAN_BLOCKS) g_boff[lane + 32] = x1 - v1;
        if (lane == 0) g_rowstart[0] = 0;
    }
}

// ---------------- K4: block-local scan + offset -> rowstart / cursor --------
__global__ __launch_bounds__(1024) void scan3_kernel() {
    __shared__ int wsum[32];
    int tid = threadIdx.x, lane = tid & 31, w = tid >> 5;
    int idx = blockIdx.x * 1024 + tid;
    int v = (idx < NN) ? g_deg[idx] : 0;
    int x = v;
#pragma unroll
    for (int off = 1; off < 32; off <<= 1) {
        int y = __shfl_up_sync(0xffffffffu, x, off);
        if (lane >= off) x += y;
    }
    if (lane == 31) wsum[w] = x;
    __syncthreads();
    if (w == 0) {
        int z = wsum[lane];
#pragma unroll
        for (int off = 1; off < 32; off <<= 1) {
            int y = __shfl_up_sync(0xffffffffu, z, off);
            if (lane >= off) z += y;
        }
        wsum[lane] = z;
    }
    __syncthreads();
    int incl = x + ((w > 0) ? wsum[w - 1] : 0) + g_boff[blockIdx.x];
    if (idx < NN) {
        g_rowstart[idx + 1] = incl;
        g_cursor[idx]       = incl - v;
    }
}

// ---------------- K5: place edges into CSR ----------------------------------
__global__ void place_kernel(const int* __restrict__ src,
                             const int* __restrict__ dst) {
    int e = blockIdx.x * blockDim.x + threadIdx.x;
    if (e < EE) {
        int d = dst[e];
        int p = atomicAdd(&g_cursor[d], 1);
        g_csr[p] = src[e];
    }
}

// ---------------- K6: fused HMMA GEMMs, pure fp16 single pass ----------------
static constexpr int ST_A   = 0;
static constexpr int ST_W   = 16384;
static constexpr int ST_STRIDE = 32768;
static constexpr int SM_BIAS_OFF = 2 * ST_STRIDE;          // 65536
static constexpr int SM_GEMM_TOTAL = SM_BIAS_OFF + 512;    // 66048

template <int K, bool OUT_HALF>
__device__ __forceinline__ void gemm_body(
    int blk, char* smem, uint32_t sb,
    const __half* A, const __half* W,
    void* out_v, const float* bias) {
    constexpr int CH = K / 64;
    constexpr int KV = K / 8;

    int tid = threadIdx.x;
    int wid = tid >> 5;
    int lane = tid & 31;
    int warp_m = wid & 3;
    int warp_n = wid >> 2;
    int g  = lane >> 3;
    int ri = lane & 7;

    const uint4* A4 = (const uint4*)A;
    const uint4* W4 = (const uint4*)W;

    if (tid < 128) ((float*)(smem + SM_BIAS_OFF))[tid] = bias[tid];

    int base = blk * 128;

    auto prefetch = [&](int c, int buf) {
        uint32_t st = sb + buf * ST_STRIDE;
#pragma unroll
        for (int it = 0; it < 4; ++it) {
            int idx = tid + it * 256;
            int row = idx >> 3;
            int kq  = idx & 7;
            uint32_t off = SMEM_SWIZZLE_128B((uint32_t)(row * 128 + kq * 16));
            int gn = base + row;
            if (gn >= NN) gn = NN - 1;
            size_t gidx = (size_t)gn * KV + c * 8 + kq;
            size_t widx = (size_t)row * KV + c * 8 + kq;
            cp_async16(st + ST_A + off, A4 + gidx);
            cp_async16(st + ST_W + off, W4 + widx);
        }
        cp_commit();
    };

    float acc[2][8][4];
#pragma unroll
    for (int mi = 0; mi < 2; mi++)
#pragma unroll
        for (int nb = 0; nb < 8; nb++)
#pragma unroll
            for (int q = 0; q < 4; q++) acc[mi][nb][q] = 0.f;

    prefetch(0, 0);

    for (int c = 0; c < CH; ++c) {
        if (c + 1 < CH) {
            prefetch(c + 1, (c + 1) & 1);
            cp_wait<1>();
        } else {
            cp_wait<0>();
        }
        __syncthreads();

        uint32_t st = sb + (c & 1) * ST_STRIDE;

#pragma unroll
        for (int ks = 0; ks < 4; ++ks) {
            uint32_t a_f[2][4];
#pragma unroll
            for (int mi = 0; mi < 2; ++mi) {
                int row = warp_m * 32 + mi * 16 + ((g & 1) << 3) + ri;
                int kb  = ks * 32 + ((g >> 1) << 4);
                uint32_t off = SMEM_SWIZZLE_128B((uint32_t)(row * 128 + kb));
                ldsm_x4(a_f[mi], st + ST_A + off);
            }
            uint32_t b[8][2];
#pragma unroll
            for (int nb2 = 0; nb2 < 4; ++nb2) {
                int row = warp_n * 64 + nb2 * 16 + ((g >> 1) << 3) + ri;
                int kb  = ks * 32 + ((g & 1) << 4);
                uint32_t off = SMEM_SWIZZLE_128B((uint32_t)(row * 128 + kb));
                uint32_t r[4];
                ldsm_x4(r, st + ST_W + off);
                b[nb2 * 2 + 0][0] = r[0];
                b[nb2 * 2 + 0][1] = r[1];
                b[nb2 * 2 + 1][0] = r[2];
                b[nb2 * 2 + 1][1] = r[3];
            }
#pragma unroll
            for (int mi = 0; mi < 2; ++mi)
#pragma unroll
                for (int nb = 0; nb < 8; ++nb)
                    mma_f16(acc[mi][nb], a_f[mi], b[nb]);
        }
        __syncthreads();
    }

    const float* bias_s = (const float*)(smem + SM_BIAS_OFF);
    int qrow = lane >> 2;
    int qcol = (lane & 3) * 2;
#pragma unroll
    for (int mi = 0; mi < 2; ++mi) {
#pragma unroll
        for (int nb = 0; nb < 8; ++nb) {
            int col = warp_n * 64 + nb * 8 + qcol;
            float b0 = bias_s[col], b1 = bias_s[col + 1];
            int r0 = base + warp_m * 32 + mi * 16 + qrow;
            int r1 = r0 + 8;
            if (OUT_HALF) {
                __half* out = (__half*)out_v;
                if (r0 < NN)
                    *(__half2*)(out + (size_t)r0 * DD + col) =
                        __floats2half2_rn(acc[mi][nb][0] + b0, acc[mi][nb][1] + b1);
                if (r1 < NN)
                    *(__half2*)(out + (size_t)r1 * DD + col) =
                        __floats2half2_rn(acc[mi][nb][2] + b0, acc[mi][nb][3] + b1);
            } else {
                float* out = (float*)out_v;
                if (r0 < NN)
                    *(float2*)(out + (size_t)r0 * DD + col) =
                        make_float2(acc[mi][nb][0] + b0, acc[mi][nb][1] + b1);
                if (r1 < NN)
                    *(float2*)(out + (size_t)r1 * DD + col) =
                        make_float2(acc[mi][nb][2] + b0, acc[mi][nb][3] + b1);
            }
        }
    }
}

__global__ __launch_bounds__(256, 2)
void gemm_fused_kernel(const float* __restrict__ lin_b,
                       const float* __restrict__ conv_b) {
    extern __shared__ char smem[];
    uint32_t sb = smem_to_u32(smem);
    if (blockIdx.x < G1_BLOCKS) {
        gemm_body<128, true>(blockIdx.x, smem, sb, g_A1, g_W1,
                             g_transformed, lin_b);
    } else {
        gemm_body<384, false>(blockIdx.x - G1_BLOCKS, smem, sb, g_A2,
                              g_W2, g_conv, conv_b);
    }
}

// ---------------- K7: gather(fp16) + mean + conv add + expmap0 ---------------
__global__ void finalize_kernel(const float* __restrict__ curv,
                                float* __restrict__ out) {
    int n = (blockIdx.x * blockDim.x + threadIdx.x) >> 5;
    int lane = threadIdx.x & 31;
    if (n >= NN) return;

    int s = g_rowstart[n];
    int e = g_rowstart[n + 1];
    const uint2* T = (const uint2*)g_transformed;   // 4 halves per lane

    float4 a = make_float4(0.f, 0.f, 0.f, 0.f);
    int p = s;
    for (; p + 4 <= e; p += 4) {
        int i0 = g_csr[p + 0], i1 = g_csr[p + 1];
        int i2 = g_csr[p + 2], i3 = g_csr[p + 3];
        uint2 u0 = T[i0 * 32 + lane];
        uint2 u1 = T[i1 * 32 + lane];
        uint2 u2 = T[i2 * 32 + lane];
        uint2 u3 = T[i3 * 32 + lane];
        __half2 h;
        float2 f;
#define ACC_U(u) \
        h = *(__half2*)&(u).x; f = __half22float2(h); a.x += f.x; a.y += f.y; \
        h = *(__half2*)&(u).y; f = __half22float2(h); a.z += f.x; a.w += f.y;
        ACC_U(u0) ACC_U(u1) ACC_U(u2) ACC_U(u3)
    }
    for (; p < e; ++p) {
        int i0 = g_csr[p];
        uint2 u0 = T[i0 * 32 + lane];
        __half2 h;
        float2 f;
        ACC_U(u0)
#undef ACC_U
    }

    float inv = (e > s) ? 1.0f / (float)(e - s) : 0.0f;
    float4 cv = ((const float4*)g_conv)[n * 32 + lane];
    float4 v = make_float4(cv.x + a.x * inv, cv.y + a.y * inv,
                           cv.z + a.z * inv, cv.w + a.w * inv);

    float ss = v.x * v.x + v.y * v.y + v.z * v.z + v.w * v.w;
#pragma unroll
    for (int off = 16; off; off >>= 1) ss += __shfl_xor_sync(0xffffffffu, ss, off);

    float c  = fabsf(curv[0]);
    float sc = sqrtf(c);
    float un = fmaxf(sqrtf(ss), 1e-15f);
    float arg = sc * un;
    float f2 = tanhf(arg) / arg;

    ((float4*)out)[n * 32 + lane] =
        make_float4(v.x * f2, v.y * f2, v.z * f2, v.w * f2);
}

// ---------------- launch: EXACT R10/R15 topology -----------------------------
extern "C" void kernel_launch(void* const* d_in, const int* in_sizes, int n_in,
                              void* d_out, int out_size) {
    const float* node   = (const float*)d_in[0];
    const float* h1     = (const float*)d_in[1];
    const float* h2     = (const float*)d_in[2];
    const float* h3     = (const float*)d_in[3];
    const float* lin_w  = (const float*)d_in[4];
    const float* lin_b  = (const float*)d_in[5];
    const float* conv_w = (const float*)d_in[6];
    const float* conv_b = (const float*)d_in[7];
    const float* curv   = (const float*)d_in[8];
    const int*   esrc   = (const int*)d_in[9];
    const int*   edst   = (const int*)d_in[10];
    float* out = (float*)d_out;

    static cudaStream_t s2 = nullptr;
    static cudaEvent_t evA = nullptr, evB = nullptr;
    if (s2 == nullptr) {
        cudaStreamCreateWithFlags(&s2, cudaStreamNonBlocking);
        cudaEventCreateWithFlags(&evA, cudaEventDisableTiming);
        cudaEventCreateWithFlags(&evB, cudaEventDisableTiming);
        cudaFuncSetAttribute(gemm_fused_kernel,
                             cudaFuncAttributeMaxDynamicSharedMemorySize,
                             SM_GEMM_TOTAL);
    }

    prep_kernel<<<(DD * DD + 3 * DD * DD + 255) / 256, 256>>>(lin_w, conv_w);
    tangent_deg_kernel<<<DEG_BLOCKS + TAN_BLOCKS, 256>>>(node, h1, h2, h3, curv, edst);

    // fork: CSR pipeline on s2, GEMM on main stream
    cudaEventRecord(evA, 0);
    cudaStreamWaitEvent(s2, evA, 0);

    scan12_kernel<<<SCAN_BLOCKS, 1024, 0, s2>>>();
    scan3_kernel<<<SCAN_BLOCKS, 1024, 0, s2>>>();
    place_kernel<<<DEG_BLOCKS, 256, 0, s2>>>(esrc, edst);

    gemm_fused_kernel<<<2 * G1_BLOCKS, 256, SM_GEMM_TOTAL>>>(lin_b, conv_b);

    // join
    cudaEventRecord(evB, s2);
    cudaStreamWaitEvent(0, evB, 0);

    finalize_kernel<<<(NN + 7) / 8, 256>>>(curv, out);
}